// round 15
// baseline (speedup 1.0000x reference)
#include <cuda_runtime.h>
#include <cuda_fp16.h>
#include <math.h>
#include <stdint.h>

#define B_  2
#define N_  2048
#define C_  768
#define H_  12
#define D_  64
#define BH_ 24

// ---------------- scratch (device globals) ---------------------------------
__device__ __half g_x16 [B_*N_*C_];
__device__ __half g_qw16[3*C_*C_];
__device__ __half g_pw16[C_*C_];
__device__ __half g_q [BH_*N_*D_];
__device__ __half g_k [BH_*N_*D_];
__device__ __half g_v [BH_*N_*D_];
__device__ __half g_o1[BH_*N_*D_];
__device__ __half g_st[BH_*N_*D_];
__device__ __half g_o2[BH_*N_*D_];

// ---------------- helpers ---------------------------------------------------
__device__ __forceinline__ uint32_t smem_u32(const void* p) {
    uint32_t a;
    asm("{ .reg .u64 t; cvta.to.shared.u64 t, %1; cvt.u32.u64 %0, t; }" : "=r"(a) : "l"(p));
    return a;
}
__device__ __forceinline__ float ex2a(float x) {
    float r;
    asm("ex2.approx.f32 %0, %1;" : "=f"(r) : "f"(x));
    return r;
}
__device__ __forceinline__ uint32_t pack2(float lo, float hi) {
    __half2 h = __floats2half2_rn(lo, hi);
    return *(uint32_t*)&h;
}
__device__ __forceinline__ void cpa16(uint32_t dst, const void* src) {
    asm volatile("cp.async.cg.shared.global [%0], [%1], 16;" :: "r"(dst), "l"(src));
}
#define CPA_COMMIT() asm volatile("cp.async.commit_group;" ::: "memory")
#define CPA_WAIT0()  asm volatile("cp.async.wait_group 0;" ::: "memory")

// D += A(16x16) * B(16x8), fp16 inputs, f32 accum
__device__ __forceinline__ void mma16(float* d, const uint32_t* a, const uint32_t* b) {
    asm volatile(
        "mma.sync.aligned.m16n8k16.row.col.f32.f16.f16.f32 "
        "{%0,%1,%2,%3}, {%4,%5,%6,%7}, {%8,%9}, {%0,%1,%2,%3};"
        : "+f"(d[0]), "+f"(d[1]), "+f"(d[2]), "+f"(d[3])
        : "r"(a[0]), "r"(a[1]), "r"(a[2]), "r"(a[3]), "r"(b[0]), "r"(b[1]));
}
__device__ __forceinline__ void ldm4(uint32_t* r, uint32_t addr) {
    asm volatile("ldmatrix.sync.aligned.m8n8.x4.shared.b16 {%0,%1,%2,%3}, [%4];"
                 : "=r"(r[0]), "=r"(r[1]), "=r"(r[2]), "=r"(r[3]) : "r"(addr));
}
__device__ __forceinline__ void ldm4t(uint32_t* r, uint32_t addr) {
    asm volatile("ldmatrix.sync.aligned.m8n8.x4.trans.shared.b16 {%0,%1,%2,%3}, [%4];"
                 : "=r"(r[0]), "=r"(r[1]), "=r"(r[2]), "=r"(r[3]) : "r"(addr));
}

// ---------------------------------------------------------------------------
// fp32 -> fp16 conversion: single kernel for x / qkv_w / proj_w
// ---------------------------------------------------------------------------
#define NX2 (B_*N_*C_/2)
#define NQ2 (3*C_*C_/2)
#define NP2 (C_*C_/2)

__global__ void __launch_bounds__(256) f2h3_kernel(
    const float* __restrict__ xs, const float* __restrict__ qs,
    const float* __restrict__ ps)
{
    int i = blockIdx.x * blockDim.x + threadIdx.x;
    if (i < NX2) {
        float2 v = ((const float2*)xs)[i];
        ((__half2*)g_x16)[i] = __floats2half2_rn(v.x, v.y);
    } else if (i < NX2 + NQ2) {
        int j = i - NX2;
        float2 v = ((const float2*)qs)[j];
        ((__half2*)g_qw16)[j] = __floats2half2_rn(v.x, v.y);
    } else if (i < NX2 + NQ2 + NP2) {
        int j = i - NX2 - NQ2;
        float2 v = ((const float2*)ps)[j];
        ((__half2*)g_pw16)[j] = __floats2half2_rn(v.x, v.y);
    }
}

// ---------------------------------------------------------------------------
// fp16 GEMM, cp.async double-buffered.  BM=BN=128, BK=64, 8 warps 2x4,
// warp tile 64x32.  Tile row stride 72 halves (144B).
// MODE 0: A=g_x16 [B*N,C], W=g_qw16  -> scatter g_q/g_k/g_v (fp16)
// MODE 1: A=g_o1 gathered, W=g_pw16  -> FUSED L2-normalize -> g_st (fp16)
// MODE 2: A=g_o2 gathered, W=g_pw16  -> d_out (fp32)
// ---------------------------------------------------------------------------
#define GEMM_SMEM (4 * 128 * 72 * 2)   // A0,A1,W0,W1 tiles

template<int MODE>
__global__ void __launch_bounds__(256, 2) gemm_mma(
    const float* __restrict__ bias, float* __restrict__ out)
{
    extern __shared__ __half smem[];
    const uint32_t sb = smem_u32(smem);
    const uint32_t A0 = sb, A1 = sb + 128*144, W0 = sb + 2*128*144, W1 = sb + 3*128*144;

    const int tid = threadIdx.x, w = tid >> 5, lane = tid & 31;
    const int g = lane >> 2, tig = lane & 3;
    const int bm = blockIdx.y * 128, bn = blockIdx.x * 128;
    const int wm = (w >> 2) * 64, wn = (w & 3) * 32;
    const int lrow = lane & 15, lc16 = (lane >> 4) * 16;

    const __half* A16 = (MODE == 0) ? g_x16 : ((MODE == 1) ? g_o1 : g_o2);
    const __half* W16 = (MODE == 0) ? g_qw16 : g_pw16;

    auto issue_tile = [&](uint32_t abuf, uint32_t wbuf, int k0) {
#pragma unroll
        for (int i = 0; i < 4; i++) {
            int c = tid + i * 256;
            int r = c >> 3, cc = c & 7;
            uint32_t doff = (uint32_t)(r * 144 + cc * 16);
            const __half* asrc;
            if (MODE == 0) {
                asrc = A16 + (size_t)(bm + r) * C_ + k0 + cc * 8;
            } else {
                int m = bm + r, nn = m >> 1, bb = m & 1, h = k0 >> 6;
                asrc = A16 + (((size_t)(bb * H_ + h)) * N_ + nn) * D_ + cc * 8;
            }
            cpa16(abuf + doff, asrc);
            cpa16(wbuf + doff, W16 + (size_t)(bn + r) * C_ + k0 + cc * 8);
        }
        CPA_COMMIT();
    };

    float acc[4][4][4];
#pragma unroll
    for (int mi = 0; mi < 4; mi++)
#pragma unroll
        for (int nj = 0; nj < 4; nj++)
#pragma unroll
            for (int c = 0; c < 4; c++) acc[mi][nj][c] = 0.f;

    issue_tile(A0, W0, 0);

    for (int k0 = 0; k0 < C_; k0 += 64) {
        const int buf = (k0 >> 6) & 1;
        const uint32_t ab = buf ? A1 : A0, wb = buf ? W1 : W0;
        CPA_WAIT0();
        __syncthreads();
        if (k0 + 64 < C_)
            issue_tile(buf ? A0 : A1, buf ? W0 : W1, k0 + 64);

#pragma unroll
        for (int ks = 0; ks < 4; ks++) {
            uint32_t af[4][4], bf[2][4];
#pragma unroll
            for (int mi = 0; mi < 4; mi++)
                ldm4(af[mi], ab + (uint32_t)((wm + 16*mi + lrow) * 144 + ks * 32 + lc16));
#pragma unroll
            for (int p = 0; p < 2; p++)
                ldm4(bf[p], wb + (uint32_t)((wn + 16*p + lrow) * 144 + ks * 32 + lc16));
#pragma unroll
            for (int mi = 0; mi < 4; mi++)
#pragma unroll
                for (int nj = 0; nj < 4; nj++) {
                    uint32_t bb2[2] = { bf[nj >> 1][(nj & 1)], bf[nj >> 1][(nj & 1) + 2] };
                    mma16(acc[mi][nj], af[mi], bb2);
                }
        }
    }

    if (MODE == 1) {
        // fused L2-normalize epilogue: CTA tile = 128 rows x 128 cols = 2 heads.
        float* P = (float*)smem;          // [128][4] row partials (reuse smem)
        const int wc = wn >> 5;
        const int hbase = (wn >> 6) * 2;
        __syncthreads();                  // tiles fully consumed
#pragma unroll
        for (int mi = 0; mi < 4; mi++) {
            float s0 = 0.f, s1 = 0.f;
#pragma unroll
            for (int nj = 0; nj < 4; nj++) {
                int c0 = bn + wn + 8 * nj + 2 * tig;
                float bx = bias[c0], by = bias[c0 + 1];
                acc[mi][nj][0] += bx; acc[mi][nj][1] += by;
                acc[mi][nj][2] += bx; acc[mi][nj][3] += by;
                s0 += acc[mi][nj][0]*acc[mi][nj][0] + acc[mi][nj][1]*acc[mi][nj][1];
                s1 += acc[mi][nj][2]*acc[mi][nj][2] + acc[mi][nj][3]*acc[mi][nj][3];
            }
            s0 += __shfl_xor_sync(0xffffffffu, s0, 1);
            s0 += __shfl_xor_sync(0xffffffffu, s0, 2);
            s1 += __shfl_xor_sync(0xffffffffu, s1, 1);
            s1 += __shfl_xor_sync(0xffffffffu, s1, 2);
            if (tig == 0) {
                P[(wm + 16*mi + g) * 4 + wc]     = s0;
                P[(wm + 16*mi + g + 8) * 4 + wc] = s1;
            }
        }
        __syncthreads();
#pragma unroll
        for (int mi = 0; mi < 4; mi++) {
            int lr0 = wm + 16*mi + g, lr1 = lr0 + 8;
            float inv0 = 1.f / fmaxf(sqrtf(P[lr0*4 + hbase] + P[lr0*4 + hbase + 1]), 1e-12f);
            float inv1 = 1.f / fmaxf(sqrtf(P[lr1*4 + hbase] + P[lr1*4 + hbase + 1]), 1e-12f);
            int r0 = bm + lr0, r1 = bm + lr1;
#pragma unroll
            for (int nj = 0; nj < 4; nj++) {
                int c0 = bn + wn + 8 * nj + 2 * tig;
                int h = c0 >> 6, d = c0 & 63;
                int nn0 = r0 >> 1, bb0 = r0 & 1;
                int nn1 = r1 >> 1, bb1 = r1 & 1;
                *(__half2*)(g_st + (((size_t)(bb0*H_ + h))*N_ + nn0)*D_ + d) =
                    __floats2half2_rn(acc[mi][nj][0]*inv0, acc[mi][nj][1]*inv0);
                *(__half2*)(g_st + (((size_t)(bb1*H_ + h))*N_ + nn1)*D_ + d) =
                    __floats2half2_rn(acc[mi][nj][2]*inv1, acc[mi][nj][3]*inv1);
            }
        }
        return;
    }

    // epilogue MODE 0 / 2
#pragma unroll
    for (int mi = 0; mi < 4; mi++) {
        int r0 = bm + wm + 16 * mi + g;
        int r1 = r0 + 8;
#pragma unroll
        for (int nj = 0; nj < 4; nj++) {
            int c0 = bn + wn + 8 * nj + 2 * tig;
            float bx = bias[c0], by = bias[c0 + 1];
            float a0 = acc[mi][nj][0] + bx, a1 = acc[mi][nj][1] + by;
            float a2 = acc[mi][nj][2] + bx, a3 = acc[mi][nj][3] + by;
            if (MODE == 0) {
                int part = c0 / C_, jq = c0 - part * C_;
                int h = jq >> 6, d = jq & 63;
                __half* base = (part == 0) ? g_q : ((part == 1) ? g_k : g_v);
                int bb0 = r0 >> 11, nn0 = r0 & (N_ - 1);
                int bb1 = r1 >> 11, nn1 = r1 & (N_ - 1);
                *(__half2*)(base + (((size_t)(bb0*H_ + h))*N_ + nn0)*D_ + d) = __floats2half2_rn(a0, a1);
                *(__half2*)(base + (((size_t)(bb1*H_ + h))*N_ + nn1)*D_ + d) = __floats2half2_rn(a2, a3);
            } else {
                int nn0 = r0 >> 1, bb0 = r0 & 1;
                int nn1 = r1 >> 1, bb1 = r1 & 1;
                *(float2*)(out + ((size_t)bb0*N_ + nn0)*C_ + c0) = make_float2(a0, a1);
                *(float2*)(out + ((size_t)bb1*N_ + nn1)*C_ + c0) = make_float2(a2, a3);
            }
        }
    }
}

// ---------------------------------------------------------------------------
// fp16 flash attention: 4 warps x 64 q-rows per CTA, 64 keys/iter.
// FUSED per-16-key-group S -> exp -> O pipeline (live sacc = 8 regs) to cut
// registers and interleave tensor/MUFU work.  Q staged through the K1/V1
// double-buffer slot (no dedicated Q buffer): smem = 36 KB -> 5+ CTAs/SM.
// STAGE 1: Q=g_q K=g_k scale .125 -> g_o1 (fp16)
// STAGE 2: Q=K=g_st scale 10, mask s<0 -> g_o2 (fp16)
// ---------------------------------------------------------------------------
template<int STAGE>
__global__ void __launch_bounds__(128, 5) flash_mma()
{
    __shared__ __half sbuf[4 * 64 * 72];
    const uint32_t sb = smem_u32(sbuf);
    const uint32_t K0 = sb,            K1 = sb + 64*144;
    const uint32_t V0 = sb + 2*64*144, V1 = sb + 3*64*144;

    const int tid = threadIdx.x, w = tid >> 5, lane = tid & 31;
    const int g = lane >> 2, tig = lane & 3;
    const int bh = blockIdx.y, row0 = blockIdx.x * 64;
    const int wm = w * 16;
    const int lrow = lane & 15, lc16 = (lane >> 4) * 16;
    const int vrow = ((lane >> 3) & 1) * 8 + (lane & 7), vc16 = (lane >> 4) * 16;

    const __half* Q  = (STAGE == 1) ? g_q : g_st;
    const __half* Kp = (STAGE == 1) ? g_k : g_st;
    __half*       O  = (STAGE == 1) ? g_o1 : g_o2;

    const __half* Qg = Q  + ((size_t)bh * N_ + row0) * D_;
    const __half* Kg = Kp + (size_t)bh * N_ * D_;
    const __half* Vg = g_v + (size_t)bh * N_ * D_;

    auto issue_kv = [&](uint32_t kbuf, uint32_t vbuf, int kt) {
#pragma unroll
        for (int i = 0; i < 4; i++) {
            int c = tid + i * 128;
            int r = c >> 3, cc = c & 7;
            uint32_t doff = (uint32_t)(r * 144 + cc * 16);
            cpa16(kbuf + doff, Kg + (size_t)(kt + r) * D_ + cc * 8);
            cpa16(vbuf + doff, Vg + (size_t)(kt + r) * D_ + cc * 8);
        }
        CPA_COMMIT();
    };

    // prologue: Q staged into K1 slot (overwritten only after qf hoist+sync)
#pragma unroll
    for (int i = 0; i < 4; i++) {
        int c = tid + i * 128;
        int r = c >> 3, cc = c & 7;
        cpa16(K1 + (uint32_t)(r * 144 + cc * 16), Qg + (size_t)r * D_ + cc * 8);
    }
    issue_kv(K0, V0, 0);   // same commit group as Q chunks
    CPA_WAIT0();
    __syncthreads();       // all threads' staging visible

    // hoist Q fragments (16 regs)
    uint32_t qf[4][4];
#pragma unroll
    for (int ks = 0; ks < 4; ks++)
        ldm4(qf[ks], K1 + (uint32_t)((wm + lrow) * 144 + ks * 32 + lc16));
    __syncthreads();       // qf hoisted everywhere before K1 is overwritten

    float oacc[8][4];
#pragma unroll
    for (int nj = 0; nj < 8; nj++)
#pragma unroll
        for (int c = 0; c < 4; c++) oacc[nj][c] = 0.f;
    float rlo = 0.f, rhi = 0.f;

    for (int kt = 0; kt < N_; kt += 64) {
        const int buf = (kt >> 6) & 1;
        const uint32_t kb = buf ? K1 : K0, vb = buf ? V1 : V0;
        if (kt > 0) { CPA_WAIT0(); __syncthreads(); }
        if (kt + 64 < N_)
            issue_kv(buf ? K0 : K1, buf ? V0 : V1, kt + 64);

        // fused per-16-key-group: S -> exp -> pack -> O
#pragma unroll
        for (int p = 0; p < 4; p++) {
            float s0[4] = {0.f, 0.f, 0.f, 0.f};
            float s1[4] = {0.f, 0.f, 0.f, 0.f};
#pragma unroll
            for (int ks = 0; ks < 4; ks++) {
                uint32_t km[4];
                ldm4(km, kb + (uint32_t)((16*p + lrow) * 144 + ks * 32 + lc16));
                uint32_t b0[2] = { km[0], km[2] };
                uint32_t b1[2] = { km[1], km[3] };
                mma16(s0, qf[ks], b0);
                mma16(s1, qf[ks], b1);
            }
            if (STAGE == 1) {
#pragma unroll
                for (int c = 0; c < 4; c++) {
                    s0[c] = ex2a(s0[c] * 0.18033688011112042f);
                    s1[c] = ex2a(s1[c] * 0.18033688011112042f);
                }
            } else {
#pragma unroll
                for (int c = 0; c < 4; c++) {
                    float a = s0[c], b = s1[c];
                    s0[c] = (a < 0.f) ? 0.f : ex2a(a * 14.426950408889634f);
                    s1[c] = (b < 0.f) ? 0.f : ex2a(b * 14.426950408889634f);
                }
            }
            rlo += s0[0] + s0[1] + s1[0] + s1[1];
            rhi += s0[2] + s0[3] + s1[2] + s1[3];

            uint32_t ap[4];
            ap[0] = pack2(s0[0], s0[1]);
            ap[1] = pack2(s0[2], s0[3]);
            ap[2] = pack2(s1[0], s1[1]);
            ap[3] = pack2(s1[2], s1[3]);
#pragma unroll
            for (int dh = 0; dh < 4; dh++) {
                uint32_t vm[4];
                ldm4t(vm, vb + (uint32_t)((p * 16 + vrow) * 144 + dh * 32 + vc16));
                mma16(oacc[2*dh],     ap, &vm[0]);
                mma16(oacc[2*dh + 1], ap, &vm[2]);
            }
        }
    }

    rlo += __shfl_xor_sync(0xffffffffu, rlo, 1);
    rlo += __shfl_xor_sync(0xffffffffu, rlo, 2);
    rhi += __shfl_xor_sync(0xffffffffu, rhi, 1);
    rhi += __shfl_xor_sync(0xffffffffu, rhi, 2);
    float ilo = 1.f / rlo, ihi = 1.f / rhi;

    __half* Ob = O + ((size_t)bh * N_ + row0 + wm + g) * D_;
#pragma unroll
    for (int nj = 0; nj < 8; nj++) {
        int c0 = 8 * nj + 2 * tig;
        *(__half2*)(Ob + c0) = __floats2half2_rn(oacc[nj][0] * ilo, oacc[nj][1] * ilo);
        *(__half2*)(Ob + (size_t)8 * D_ + c0) = __floats2half2_rn(oacc[nj][2] * ihi, oacc[nj][3] * ihi);
    }
}

// ---------------------------------------------------------------------------
extern "C" void kernel_launch(void* const* d_in, const int* in_sizes, int n_in,
                              void* d_out, int out_size)
{
    const float* x      = (const float*)d_in[0];
    const float* qkv_w  = (const float*)d_in[1];
    const float* qkv_b  = (const float*)d_in[2];
    const float* proj_w = (const float*)d_in[3];
    const float* proj_b = (const float*)d_in[4];
    float* out = (float*)d_out;

    cudaFuncSetAttribute(gemm_mma<0>, cudaFuncAttributeMaxDynamicSharedMemorySize, GEMM_SMEM);
    cudaFuncSetAttribute(gemm_mma<1>, cudaFuncAttributeMaxDynamicSharedMemorySize, GEMM_SMEM);
    cudaFuncSetAttribute(gemm_mma<2>, cudaFuncAttributeMaxDynamicSharedMemorySize, GEMM_SMEM);

    // 0) fp32 -> fp16 pre-pass (single kernel for all three arrays)
    f2h3_kernel<<<(NX2 + NQ2 + NP2 + 255) / 256, 256>>>(x, qkv_w, proj_w);

    // 1) QKV GEMM -> g_q/g_k/g_v (fp16, head layout)
    gemm_mma<0><<<dim3(18, 32), 256, GEMM_SMEM>>>(qkv_b, nullptr);
    // 2) stage-1 attention
    flash_mma<1><<<dim3(N_ / 64, BH_), 128>>>();
    // 3) first projection + FUSED L2-normalize -> g_st (fp16)
    gemm_mma<1><<<dim3(6, 32), 256, GEMM_SMEM>>>(proj_b, nullptr);
    // 4) stage-2 self-correlation attention
    flash_mma<2><<<dim3(N_ / 64, BH_), 128>>>();
    // 5) final projection -> d_out (fp32)
    gemm_mma<2><<<dim3(6, 32), 256, GEMM_SMEM>>>(proj_b, out);
}

// round 16
// speedup vs baseline: 1.1004x; 1.1004x over previous
#include <cuda_runtime.h>
#include <cuda_fp16.h>
#include <math.h>
#include <stdint.h>

#define B_  2
#define N_  2048
#define C_  768
#define H_  12
#define D_  64
#define BH_ 24

// ---------------- scratch (device globals) ---------------------------------
__device__ __half g_x16 [B_*N_*C_];
__device__ __half g_qw16[3*C_*C_];
__device__ __half g_pw16[C_*C_];
__device__ __half g_q [BH_*N_*D_];
__device__ __half g_k [BH_*N_*D_];
__device__ __half g_v [BH_*N_*D_];
__device__ __half g_o1[BH_*N_*D_];
__device__ __half g_st[BH_*N_*D_];
__device__ __half g_o2[BH_*N_*D_];

// ---------------- helpers ---------------------------------------------------
__device__ __forceinline__ uint32_t smem_u32(const void* p) {
    uint32_t a;
    asm("{ .reg .u64 t; cvta.to.shared.u64 t, %1; cvt.u32.u64 %0, t; }" : "=r"(a) : "l"(p));
    return a;
}
__device__ __forceinline__ float ex2a(float x) {
    float r;
    asm("ex2.approx.f32 %0, %1;" : "=f"(r) : "f"(x));
    return r;
}
__device__ __forceinline__ uint32_t pack2(float lo, float hi) {
    __half2 h = __floats2half2_rn(lo, hi);
    return *(uint32_t*)&h;
}
__device__ __forceinline__ void cpa16(uint32_t dst, const void* src) {
    asm volatile("cp.async.cg.shared.global [%0], [%1], 16;" :: "r"(dst), "l"(src));
}
#define CPA_COMMIT() asm volatile("cp.async.commit_group;" ::: "memory")
#define CPA_WAIT0()  asm volatile("cp.async.wait_group 0;" ::: "memory")

// D += A(16x16) * B(16x8), fp16 inputs, f32 accum
__device__ __forceinline__ void mma16(float* d, const uint32_t* a, const uint32_t* b) {
    asm volatile(
        "mma.sync.aligned.m16n8k16.row.col.f32.f16.f16.f32 "
        "{%0,%1,%2,%3}, {%4,%5,%6,%7}, {%8,%9}, {%0,%1,%2,%3};"
        : "+f"(d[0]), "+f"(d[1]), "+f"(d[2]), "+f"(d[3])
        : "r"(a[0]), "r"(a[1]), "r"(a[2]), "r"(a[3]), "r"(b[0]), "r"(b[1]));
}
__device__ __forceinline__ void ldm4(uint32_t* r, uint32_t addr) {
    asm volatile("ldmatrix.sync.aligned.m8n8.x4.shared.b16 {%0,%1,%2,%3}, [%4];"
                 : "=r"(r[0]), "=r"(r[1]), "=r"(r[2]), "=r"(r[3]) : "r"(addr));
}
__device__ __forceinline__ void ldm4t(uint32_t* r, uint32_t addr) {
    asm volatile("ldmatrix.sync.aligned.m8n8.x4.trans.shared.b16 {%0,%1,%2,%3}, [%4];"
                 : "=r"(r[0]), "=r"(r[1]), "=r"(r[2]), "=r"(r[3]) : "r"(addr));
}

// ---------------------------------------------------------------------------
// fp32 -> fp16 conversion: single kernel for x / qkv_w / proj_w
// ---------------------------------------------------------------------------
#define NX2 (B_*N_*C_/2)
#define NQ2 (3*C_*C_/2)
#define NP2 (C_*C_/2)

__global__ void __launch_bounds__(256) f2h3_kernel(
    const float* __restrict__ xs, const float* __restrict__ qs,
    const float* __restrict__ ps)
{
    int i = blockIdx.x * blockDim.x + threadIdx.x;
    if (i < NX2) {
        float2 v = ((const float2*)xs)[i];
        ((__half2*)g_x16)[i] = __floats2half2_rn(v.x, v.y);
    } else if (i < NX2 + NQ2) {
        int j = i - NX2;
        float2 v = ((const float2*)qs)[j];
        ((__half2*)g_qw16)[j] = __floats2half2_rn(v.x, v.y);
    } else if (i < NX2 + NQ2 + NP2) {
        int j = i - NX2 - NQ2;
        float2 v = ((const float2*)ps)[j];
        ((__half2*)g_pw16)[j] = __floats2half2_rn(v.x, v.y);
    }
}

// ---------------------------------------------------------------------------
// QKV GEMM (MODE-0 only): BM=BN=128, BK=64, 8 warps 2x4, warp tile 64x32.
// A=g_x16 [B*N,C], W=g_qw16 -> scatter g_q/g_k/g_v (fp16)
// ---------------------------------------------------------------------------
#define GEMM_SMEM (4 * 128 * 72 * 2)   // A0,A1,W0,W1 tiles

__global__ void __launch_bounds__(256, 2) gemm_qkv(const float* __restrict__ bias)
{
    extern __shared__ __half smem[];
    const uint32_t sb = smem_u32(smem);
    const uint32_t A0 = sb, A1 = sb + 128*144, W0 = sb + 2*128*144, W1 = sb + 3*128*144;

    const int tid = threadIdx.x, w = tid >> 5, lane = tid & 31;
    const int g = lane >> 2, tig = lane & 3;
    const int bm = blockIdx.y * 128, bn = blockIdx.x * 128;
    const int wm = (w >> 2) * 64, wn = (w & 3) * 32;
    const int lrow = lane & 15, lc16 = (lane >> 4) * 16;

    auto issue_tile = [&](uint32_t abuf, uint32_t wbuf, int k0) {
#pragma unroll
        for (int i = 0; i < 4; i++) {
            int c = tid + i * 256;
            int r = c >> 3, cc = c & 7;
            uint32_t doff = (uint32_t)(r * 144 + cc * 16);
            cpa16(abuf + doff, g_x16 + (size_t)(bm + r) * C_ + k0 + cc * 8);
            cpa16(wbuf + doff, g_qw16 + (size_t)(bn + r) * C_ + k0 + cc * 8);
        }
        CPA_COMMIT();
    };

    float acc[4][4][4];
#pragma unroll
    for (int mi = 0; mi < 4; mi++)
#pragma unroll
        for (int nj = 0; nj < 4; nj++)
#pragma unroll
            for (int c = 0; c < 4; c++) acc[mi][nj][c] = 0.f;

    issue_tile(A0, W0, 0);

    for (int k0 = 0; k0 < C_; k0 += 64) {
        const int buf = (k0 >> 6) & 1;
        const uint32_t ab = buf ? A1 : A0, wb = buf ? W1 : W0;
        CPA_WAIT0();
        __syncthreads();
        if (k0 + 64 < C_)
            issue_tile(buf ? A0 : A1, buf ? W0 : W1, k0 + 64);

#pragma unroll
        for (int ks = 0; ks < 4; ks++) {
            uint32_t af[4][4], bf[2][4];
#pragma unroll
            for (int mi = 0; mi < 4; mi++)
                ldm4(af[mi], ab + (uint32_t)((wm + 16*mi + lrow) * 144 + ks * 32 + lc16));
#pragma unroll
            for (int p = 0; p < 2; p++)
                ldm4(bf[p], wb + (uint32_t)((wn + 16*p + lrow) * 144 + ks * 32 + lc16));
#pragma unroll
            for (int mi = 0; mi < 4; mi++)
#pragma unroll
                for (int nj = 0; nj < 4; nj++) {
                    uint32_t bb2[2] = { bf[nj >> 1][(nj & 1)], bf[nj >> 1][(nj & 1) + 2] };
                    mma16(acc[mi][nj], af[mi], bb2);
                }
        }
    }

#pragma unroll
    for (int mi = 0; mi < 4; mi++) {
        int r0 = bm + wm + 16 * mi + g;
        int r1 = r0 + 8;
#pragma unroll
        for (int nj = 0; nj < 4; nj++) {
            int c0 = bn + wn + 8 * nj + 2 * tig;
            float bx = bias[c0], by = bias[c0 + 1];
            float a0 = acc[mi][nj][0] + bx, a1 = acc[mi][nj][1] + by;
            float a2 = acc[mi][nj][2] + bx, a3 = acc[mi][nj][3] + by;
            int part = c0 / C_, jq = c0 - part * C_;
            int h = jq >> 6, d = jq & 63;
            __half* base = (part == 0) ? g_q : ((part == 1) ? g_k : g_v);
            int bb0 = r0 >> 11, nn0 = r0 & (N_ - 1);
            int bb1 = r1 >> 11, nn1 = r1 & (N_ - 1);
            *(__half2*)(base + (((size_t)(bb0*H_ + h))*N_ + nn0)*D_ + d) = __floats2half2_rn(a0, a1);
            *(__half2*)(base + (((size_t)(bb1*H_ + h))*N_ + nn1)*D_ + d) = __floats2half2_rn(a2, a3);
        }
    }
}

// ---------------------------------------------------------------------------
// Projection GEMM: BM=64, BN=128, BK=64, 128 threads (4 warps, warp 64x32).
// Grid 64x6 = 384 CTAs, 3 CTAs/SM -> single balanced wave (384 <= 444).
// MODE 1: A=g_o1 gathered -> FUSED L2-normalize -> g_st (fp16)
// MODE 2: A=g_o2 gathered -> d_out (fp32)
// ---------------------------------------------------------------------------
#define PROJ_SMEM (2 * (64 + 128) * 144)   // (A 64 + W 128 rows) x 2 buffers

template<int MODE>
__global__ void __launch_bounds__(128, 3) proj_mma(
    const float* __restrict__ bias, float* __restrict__ out)
{
    extern __shared__ __half smem[];
    const uint32_t sb = smem_u32(smem);
    const uint32_t BUF = (64 + 128) * 144;

    const int tid = threadIdx.x, w = tid >> 5, lane = tid & 31;
    const int g = lane >> 2, tig = lane & 3;
    const int bm = blockIdx.y * 64, bn = blockIdx.x * 128;
    const int wn = w * 32;
    const int lrow = lane & 15, lc16 = (lane >> 4) * 16;

    const __half* A16 = (MODE == 1) ? g_o1 : g_o2;

    auto issue_tile = [&](int buf, int k0) {
        uint32_t ab = sb + (uint32_t)buf * BUF;
        uint32_t wb = ab + 64 * 144;
        int h = k0 >> 6;
#pragma unroll
        for (int i = 0; i < 4; i++) {       // A: 64 rows x 8 chunks = 512
            int c = tid + i * 128;
            int r = c >> 3, cc = c & 7;
            int m = bm + r, nn = m >> 1, bb = m & 1;
            cpa16(ab + (uint32_t)(r * 144 + cc * 16),
                  A16 + (((size_t)(bb * H_ + h)) * N_ + nn) * D_ + cc * 8);
        }
#pragma unroll
        for (int i = 0; i < 8; i++) {       // W: 128 rows x 8 chunks = 1024
            int c = tid + i * 128;
            int r = c >> 3, cc = c & 7;
            cpa16(wb + (uint32_t)(r * 144 + cc * 16),
                  g_pw16 + (size_t)(bn + r) * C_ + k0 + cc * 8);
        }
        CPA_COMMIT();
    };

    float acc[4][4][4];
#pragma unroll
    for (int mi = 0; mi < 4; mi++)
#pragma unroll
        for (int nj = 0; nj < 4; nj++)
#pragma unroll
            for (int c = 0; c < 4; c++) acc[mi][nj][c] = 0.f;

    issue_tile(0, 0);

    for (int k0 = 0; k0 < C_; k0 += 64) {
        const int buf = (k0 >> 6) & 1;
        const uint32_t ab = sb + (uint32_t)buf * BUF;
        const uint32_t wb = ab + 64 * 144;
        CPA_WAIT0();
        __syncthreads();
        if (k0 + 64 < C_)
            issue_tile(buf ^ 1, k0 + 64);

#pragma unroll
        for (int ks = 0; ks < 4; ks++) {
            uint32_t af[4][4], bf[2][4];
#pragma unroll
            for (int mi = 0; mi < 4; mi++)
                ldm4(af[mi], ab + (uint32_t)((16*mi + lrow) * 144 + ks * 32 + lc16));
#pragma unroll
            for (int p = 0; p < 2; p++)
                ldm4(bf[p], wb + (uint32_t)((wn + 16*p + lrow) * 144 + ks * 32 + lc16));
#pragma unroll
            for (int mi = 0; mi < 4; mi++)
#pragma unroll
                for (int nj = 0; nj < 4; nj++) {
                    uint32_t bb2[2] = { bf[nj >> 1][(nj & 1)], bf[nj >> 1][(nj & 1) + 2] };
                    mma16(acc[mi][nj], af[mi], bb2);
                }
        }
    }

    if (MODE == 1) {
        // fused L2-normalize: CTA tile = 64 rows x 128 cols = 2 complete heads.
        float* P = (float*)smem;          // [64][4] row partials (reuse smem)
        const int wc = wn >> 5;           // warp-column index 0..3
        const int hbase = (wn >> 6) * 2;  // head-pair base: {0,0,2,2}
        __syncthreads();                  // tiles fully consumed
#pragma unroll
        for (int mi = 0; mi < 4; mi++) {
            float s0 = 0.f, s1 = 0.f;
#pragma unroll
            for (int nj = 0; nj < 4; nj++) {
                int c0 = bn + wn + 8 * nj + 2 * tig;
                float bx = bias[c0], by = bias[c0 + 1];
                acc[mi][nj][0] += bx; acc[mi][nj][1] += by;
                acc[mi][nj][2] += bx; acc[mi][nj][3] += by;
                s0 += acc[mi][nj][0]*acc[mi][nj][0] + acc[mi][nj][1]*acc[mi][nj][1];
                s1 += acc[mi][nj][2]*acc[mi][nj][2] + acc[mi][nj][3]*acc[mi][nj][3];
            }
            s0 += __shfl_xor_sync(0xffffffffu, s0, 1);
            s0 += __shfl_xor_sync(0xffffffffu, s0, 2);
            s1 += __shfl_xor_sync(0xffffffffu, s1, 1);
            s1 += __shfl_xor_sync(0xffffffffu, s1, 2);
            if (tig == 0) {
                P[(16*mi + g) * 4 + wc]     = s0;
                P[(16*mi + g + 8) * 4 + wc] = s1;
            }
        }
        __syncthreads();
#pragma unroll
        for (int mi = 0; mi < 4; mi++) {
            int lr0 = 16*mi + g, lr1 = lr0 + 8;
            float inv0 = 1.f / fmaxf(sqrtf(P[lr0*4 + hbase] + P[lr0*4 + hbase + 1]), 1e-12f);
            float inv1 = 1.f / fmaxf(sqrtf(P[lr1*4 + hbase] + P[lr1*4 + hbase + 1]), 1e-12f);
            int r0 = bm + lr0, r1 = bm + lr1;
#pragma unroll
            for (int nj = 0; nj < 4; nj++) {
                int c0 = bn + wn + 8 * nj + 2 * tig;
                int h = c0 >> 6, d = c0 & 63;
                int nn0 = r0 >> 1, bb0 = r0 & 1;
                int nn1 = r1 >> 1, bb1 = r1 & 1;
                *(__half2*)(g_st + (((size_t)(bb0*H_ + h))*N_ + nn0)*D_ + d) =
                    __floats2half2_rn(acc[mi][nj][0]*inv0, acc[mi][nj][1]*inv0);
                *(__half2*)(g_st + (((size_t)(bb1*H_ + h))*N_ + nn1)*D_ + d) =
                    __floats2half2_rn(acc[mi][nj][2]*inv1, acc[mi][nj][3]*inv1);
            }
        }
        return;
    }

    // MODE 2 epilogue -> d_out [B,N,C] fp32
#pragma unroll
    for (int mi = 0; mi < 4; mi++) {
        int r0 = bm + 16*mi + g;
        int r1 = r0 + 8;
#pragma unroll
        for (int nj = 0; nj < 4; nj++) {
            int c0 = bn + wn + 8 * nj + 2 * tig;
            float bx = bias[c0], by = bias[c0 + 1];
            int nn0 = r0 >> 1, bb0 = r0 & 1;
            int nn1 = r1 >> 1, bb1 = r1 & 1;
            *(float2*)(out + ((size_t)bb0*N_ + nn0)*C_ + c0) =
                make_float2(acc[mi][nj][0] + bx, acc[mi][nj][1] + by);
            *(float2*)(out + ((size_t)bb1*N_ + nn1)*C_ + c0) =
                make_float2(acc[mi][nj][2] + bx, acc[mi][nj][3] + by);
        }
    }
}

// ---------------------------------------------------------------------------
// fp16 flash attention (R14 structure): 4 warps x 64 q-rows per CTA, 64 keys
// per iter, cp.async double-buffered K/V, Q fragments hoisted.  Static smem
// (45KB) -> 4 CTAs/SM.
// STAGE 1: Q=g_q K=g_k scale .125 -> g_o1 (fp16)
// STAGE 2: Q=K=g_st scale 10, mask s<0 -> g_o2 (fp16)
// ---------------------------------------------------------------------------
template<int STAGE>
__global__ void __launch_bounds__(128, 4) flash_mma()
{
    __shared__ __half sbuf[5 * 64 * 72];
    const uint32_t sb = smem_u32(sbuf);
    const uint32_t SQ = sb;
    const uint32_t K0 = sb + 64*144, K1 = K0 + 64*144;
    const uint32_t V0 = K1 + 64*144, V1 = V0 + 64*144;

    const int tid = threadIdx.x, w = tid >> 5, lane = tid & 31;
    const int g = lane >> 2, tig = lane & 3;
    const int bh = blockIdx.y, row0 = blockIdx.x * 64;
    const int wm = w * 16;
    const int lrow = lane & 15, lc16 = (lane >> 4) * 16;
    const int vrow = ((lane >> 3) & 1) * 8 + (lane & 7), vc16 = (lane >> 4) * 16;

    const __half* Q  = (STAGE == 1) ? g_q : g_st;
    const __half* Kp = (STAGE == 1) ? g_k : g_st;
    __half*       O  = (STAGE == 1) ? g_o1 : g_o2;

    const __half* Qg = Q  + ((size_t)bh * N_ + row0) * D_;
    const __half* Kg = Kp + (size_t)bh * N_ * D_;
    const __half* Vg = g_v + (size_t)bh * N_ * D_;

    auto issue_kv = [&](uint32_t kbuf, uint32_t vbuf, int kt) {
#pragma unroll
        for (int i = 0; i < 4; i++) {
            int c = tid + i * 128;
            int r = c >> 3, cc = c & 7;
            uint32_t doff = (uint32_t)(r * 144 + cc * 16);
            cpa16(kbuf + doff, Kg + (size_t)(kt + r) * D_ + cc * 8);
            cpa16(vbuf + doff, Vg + (size_t)(kt + r) * D_ + cc * 8);
        }
        CPA_COMMIT();
    };

    // prologue: Q + first K/V tile
#pragma unroll
    for (int i = 0; i < 4; i++) {
        int c = tid + i * 128;
        int r = c >> 3, cc = c & 7;
        cpa16(SQ + (uint32_t)(r * 144 + cc * 16), Qg + (size_t)r * D_ + cc * 8);
    }
    issue_kv(K0, V0, 0);   // commits Q chunks too (same group)
    CPA_WAIT0();
    __syncthreads();

    // hoist Q fragments (16 regs); sQ never read again
    uint32_t qf[4][4];
#pragma unroll
    for (int ks = 0; ks < 4; ks++)
        ldm4(qf[ks], SQ + (uint32_t)((wm + lrow) * 144 + ks * 32 + lc16));

    float oacc[8][4];
#pragma unroll
    for (int nj = 0; nj < 8; nj++)
#pragma unroll
        for (int c = 0; c < 4; c++) oacc[nj][c] = 0.f;
    float rlo = 0.f, rhi = 0.f;

    for (int kt = 0; kt < N_; kt += 64) {
        const int buf = (kt >> 6) & 1;
        const uint32_t kb = buf ? K1 : K0, vb = buf ? V1 : V0;
        if (kt > 0) { CPA_WAIT0(); __syncthreads(); }
        if (kt + 64 < N_)
            issue_kv(buf ? K0 : K1, buf ? V0 : V1, kt + 64);

        // S = Q K^T
        float sacc[8][4];
#pragma unroll
        for (int nj = 0; nj < 8; nj++)
#pragma unroll
            for (int c = 0; c < 4; c++) sacc[nj][c] = 0.f;
#pragma unroll
        for (int ks = 0; ks < 4; ks++) {
#pragma unroll
            for (int p = 0; p < 4; p++) {
                uint32_t km[4];
                ldm4(km, kb + (uint32_t)((16*p + lrow) * 144 + ks * 32 + lc16));
                uint32_t b0[2] = { km[0], km[2] };
                uint32_t b1[2] = { km[1], km[3] };
                mma16(sacc[2*p],     qf[ks], b0);
                mma16(sacc[2*p + 1], qf[ks], b1);
            }
        }

        // softmax numerator (scores bounded; no max subtraction)
#pragma unroll
        for (int nj = 0; nj < 8; nj++) {
            if (STAGE == 1) {
                sacc[nj][0] = ex2a(sacc[nj][0] * 0.18033688011112042f);
                sacc[nj][1] = ex2a(sacc[nj][1] * 0.18033688011112042f);
                sacc[nj][2] = ex2a(sacc[nj][2] * 0.18033688011112042f);
                sacc[nj][3] = ex2a(sacc[nj][3] * 0.18033688011112042f);
            } else {
                float s0 = sacc[nj][0], s1 = sacc[nj][1];
                float s2 = sacc[nj][2], s3 = sacc[nj][3];
                sacc[nj][0] = (s0 < 0.f) ? 0.f : ex2a(s0 * 14.426950408889634f);
                sacc[nj][1] = (s1 < 0.f) ? 0.f : ex2a(s1 * 14.426950408889634f);
                sacc[nj][2] = (s2 < 0.f) ? 0.f : ex2a(s2 * 14.426950408889634f);
                sacc[nj][3] = (s3 < 0.f) ? 0.f : ex2a(s3 * 14.426950408889634f);
            }
            rlo += sacc[nj][0] + sacc[nj][1];
            rhi += sacc[nj][2] + sacc[nj][3];
        }

        // O += P V : P packed straight from accumulators
#pragma unroll
        for (int m = 0; m < 4; m++) {
            uint32_t ap[4];
            ap[0] = pack2(sacc[2*m    ][0], sacc[2*m    ][1]);
            ap[1] = pack2(sacc[2*m    ][2], sacc[2*m    ][3]);
            ap[2] = pack2(sacc[2*m + 1][0], sacc[2*m + 1][1]);
            ap[3] = pack2(sacc[2*m + 1][2], sacc[2*m + 1][3]);
#pragma unroll
            for (int dh = 0; dh < 4; dh++) {
                uint32_t vm[4];
                ldm4t(vm, vb + (uint32_t)((m * 16 + vrow) * 144 + dh * 32 + vc16));
                mma16(oacc[2*dh],     ap, &vm[0]);
                mma16(oacc[2*dh + 1], ap, &vm[2]);
            }
        }
    }

    rlo += __shfl_xor_sync(0xffffffffu, rlo, 1);
    rlo += __shfl_xor_sync(0xffffffffu, rlo, 2);
    rhi += __shfl_xor_sync(0xffffffffu, rhi, 1);
    rhi += __shfl_xor_sync(0xffffffffu, rhi, 2);
    float ilo = 1.f / rlo, ihi = 1.f / rhi;

    __half* Ob = O + ((size_t)bh * N_ + row0 + wm + g) * D_;
#pragma unroll
    for (int nj = 0; nj < 8; nj++) {
        int c0 = 8 * nj + 2 * tig;
        *(__half2*)(Ob + c0) = __floats2half2_rn(oacc[nj][0] * ilo, oacc[nj][1] * ilo);
        *(__half2*)(Ob + (size_t)8 * D_ + c0) = __floats2half2_rn(oacc[nj][2] * ihi, oacc[nj][3] * ihi);
    }
}

// ---------------------------------------------------------------------------
extern "C" void kernel_launch(void* const* d_in, const int* in_sizes, int n_in,
                              void* d_out, int out_size)
{
    const float* x      = (const float*)d_in[0];
    const float* qkv_w  = (const float*)d_in[1];
    const float* qkv_b  = (const float*)d_in[2];
    const float* proj_w = (const float*)d_in[3];
    const float* proj_b = (const float*)d_in[4];
    float* out = (float*)d_out;

    cudaFuncSetAttribute(gemm_qkv,    cudaFuncAttributeMaxDynamicSharedMemorySize, GEMM_SMEM);
    cudaFuncSetAttribute(proj_mma<1>, cudaFuncAttributeMaxDynamicSharedMemorySize, PROJ_SMEM);
    cudaFuncSetAttribute(proj_mma<2>, cudaFuncAttributeMaxDynamicSharedMemorySize, PROJ_SMEM);

    // 0) fp32 -> fp16 pre-pass (single kernel)
    f2h3_kernel<<<(NX2 + NQ2 + NP2 + 255) / 256, 256>>>(x, qkv_w, proj_w);

    // 1) QKV GEMM -> g_q/g_k/g_v (fp16, head layout)
    gemm_qkv<<<dim3(18, 32), 256, GEMM_SMEM>>>(qkv_b);
    // 2) stage-1 attention
    flash_mma<1><<<dim3(N_ / 64, BH_), 128>>>();
    // 3) first projection + FUSED L2-normalize -> g_st (fp16)
    proj_mma<1><<<dim3(6, 64), 128, PROJ_SMEM>>>(proj_b, nullptr);
    // 4) stage-2 self-correlation attention
    flash_mma<2><<<dim3(N_ / 64, BH_), 128>>>();
    // 5) final projection -> d_out (fp32)
    proj_mma<2><<<dim3(6, 64), 128, PROJ_SMEM>>>(proj_b, out);
}